// round 1
// baseline (speedup 1.0000x reference)
#include <cuda_runtime.h>
#include <cuda_bf16.h>
#include <cstdint>

// Problem constants
#define BB      4
#define TT_ALL  512
#define SS      512
#define IN_DIM  512
#define MEM_DIM 256

// Scratch (device globals; no allocations allowed)
__device__ __align__(16) float g_wq[BB * TT_ALL * MEM_DIM];   // [B,T,256]
__device__ __align__(16) float g_uh[BB * SS * MEM_DIM];       // [B,S,256]
__device__ __align__(16) float g_c [BB * TT_ALL * MEM_DIM];   // [B,T,256]

// ---------------------------------------------------------------------------
// Tiled NT SGEMM:  C[M,N] = Acat[M,K] * B[N,K]^T (+bias)
// A rows: k < K1 -> A (pitch K1), k >= K1 -> A2 (pitch K-K1). Non-dual: A2=null, K1=K.
// Requires M%64==0, N%64==0, K%16==0 (true for all our shapes).
// ---------------------------------------------------------------------------
__global__ __launch_bounds__(256) void gemm_nt_kernel(
    const float* __restrict__ A, const float* __restrict__ A2, int K1,
    const float* __restrict__ Bm, const float* __restrict__ bias,
    float* __restrict__ C, int M, int N, int K)
{
    __shared__ float As[64][17];
    __shared__ float Bs[64][17];

    const int tid = threadIdx.x;
    const int tx = tid & 15;          // 0..15 -> N
    const int ty = tid >> 4;          // 0..15 -> M
    const int row0 = blockIdx.y * 64;
    const int col0 = blockIdx.x * 64;

    const int lrow = tid >> 2;        // 0..63
    const int lk4  = (tid & 3) * 4;   // 0,4,8,12

    float acc[4][4];
#pragma unroll
    for (int i = 0; i < 4; i++)
#pragma unroll
        for (int j = 0; j < 4; j++) acc[i][j] = 0.f;

    const int K2 = K - K1;

    for (int k0 = 0; k0 < K; k0 += 16) {
        // load A tile (64 x 16)
        {
            const int ar = row0 + lrow;
            const int ak = k0 + lk4;
            float4 av;
            if (A2 != nullptr && ak >= K1)
                av = *reinterpret_cast<const float4*>(A2 + (size_t)ar * K2 + (ak - K1));
            else
                av = *reinterpret_cast<const float4*>(A  + (size_t)ar * K1 + ak);
            As[lrow][lk4 + 0] = av.x;
            As[lrow][lk4 + 1] = av.y;
            As[lrow][lk4 + 2] = av.z;
            As[lrow][lk4 + 3] = av.w;
        }
        // load B tile (64 x 16)
        {
            const int br = col0 + lrow;
            float4 bv = *reinterpret_cast<const float4*>(Bm + (size_t)br * K + k0 + lk4);
            Bs[lrow][lk4 + 0] = bv.x;
            Bs[lrow][lk4 + 1] = bv.y;
            Bs[lrow][lk4 + 2] = bv.z;
            Bs[lrow][lk4 + 3] = bv.w;
        }
        __syncthreads();

#pragma unroll
        for (int k = 0; k < 16; k++) {
            float a[4], b[4];
#pragma unroll
            for (int i = 0; i < 4; i++) a[i] = As[ty * 4 + i][k];
#pragma unroll
            for (int j = 0; j < 4; j++) b[j] = Bs[tx * 4 + j][k];
#pragma unroll
            for (int i = 0; i < 4; i++)
#pragma unroll
                for (int j = 0; j < 4; j++) acc[i][j] = fmaf(a[i], b[j], acc[i][j]);
        }
        __syncthreads();
    }

#pragma unroll
    for (int i = 0; i < 4; i++) {
        const int r = row0 + ty * 4 + i;
#pragma unroll
        for (int j = 0; j < 4; j++) {
            const int c = col0 + tx * 4 + j;
            float o = acc[i][j];
            if (bias != nullptr) o += bias[c];
            C[(size_t)r * N + c] = o;
        }
    }
}

// ---------------------------------------------------------------------------
// Fused attention core: scores -> tanh -> dot(v) -> masked softmax -> context
// Grid: (T/TTILE, B), 512 threads. Thread owns one s.
// ---------------------------------------------------------------------------
#define TTILE 8
#define DTILE 16
#define UH_PITCH 514   // conflict-free transpose store + read

__device__ __forceinline__ float tanh_fast(float x) {
    float y;
    asm("tanh.approx.f32 %0, %1;" : "=f"(y) : "f"(x));
    return y;
}

__global__ __launch_bounds__(512) void attn_core_kernel(
    const float* __restrict__ wq,        // [B,T,256]
    const float* __restrict__ uh,        // [B,S,256]
    const float* __restrict__ mems,      // [B,S,256]
    const int*   __restrict__ mem_masks, // [B]
    const float* __restrict__ v,         // [256]
    float* __restrict__ align_out,       // [B,T,S]
    float* __restrict__ c_out)           // [B,T,256]
{
    __shared__ float wq_s[TTILE * MEM_DIM];       // 8 KB (reused as c_part)
    __shared__ float v_s[MEM_DIM];                // 1 KB
    __shared__ float buf[DTILE * UH_PITCH];       // 32.1 KB: uh tile, then p
    __shared__ float red_s[TTILE * 16];           // block reduce

    const int tid = threadIdx.x;
    const int b  = blockIdx.y;
    const int t0 = blockIdx.x * TTILE;
    const int my_s = tid;
    const int lane = tid & 31;
    const int wid  = tid >> 5;

    // stage wq rows + v
    for (int i = tid; i < TTILE * MEM_DIM; i += 512)
        wq_s[i] = wq[((size_t)(b * TT_ALL + t0 + (i >> 8)) << 8) + (i & 255)];
    for (int i = tid; i < MEM_DIM; i += 512)
        v_s[i] = v[i];

    const int mlen = mem_masks[b];

    float acc[TTILE];
#pragma unroll
    for (int t = 0; t < TTILE; t++) acc[t] = 0.f;

    // ---- score phase: acc[t] = sum_d tanh(wq[t,d] + uh[s,d]) * v[d] ----
    for (int d0 = 0; d0 < MEM_DIM; d0 += DTILE) {
        __syncthreads();
        // load uh[b, :, d0:d0+16] transposed into buf[dl][s]
#pragma unroll
        for (int it = 0; it < 4; it++) {
            const int s = (tid >> 2) + it * 128;
            const int c = tid & 3;
            float4 u4 = *reinterpret_cast<const float4*>(
                uh + ((size_t)(b * SS + s) << 8) + d0 + c * 4);
            buf[(c * 4 + 0) * UH_PITCH + s] = u4.x;
            buf[(c * 4 + 1) * UH_PITCH + s] = u4.y;
            buf[(c * 4 + 2) * UH_PITCH + s] = u4.z;
            buf[(c * 4 + 3) * UH_PITCH + s] = u4.w;
        }
        __syncthreads();

#pragma unroll
        for (int dl = 0; dl < DTILE; dl++) {
            const float u  = buf[dl * UH_PITCH + my_s];
            const float vv = v_s[d0 + dl];
#pragma unroll
            for (int t = 0; t < TTILE; t++) {
                const float x = wq_s[t * MEM_DIM + d0 + dl] + u;
                acc[t] = fmaf(tanh_fast(x), vv, acc[t]);
            }
        }
    }

    // ---- masked softmax over s (512 threads) ----
    const bool valid = (my_s < mlen);
    float sc[TTILE];
#pragma unroll
    for (int t = 0; t < TTILE; t++) sc[t] = valid ? acc[t] : -1e30f;

    float mx[TTILE];
#pragma unroll
    for (int t = 0; t < TTILE; t++) {
        float m = sc[t];
#pragma unroll
        for (int o = 16; o > 0; o >>= 1) m = fmaxf(m, __shfl_xor_sync(0xffffffffu, m, o));
        if (lane == 0) red_s[t * 16 + wid] = m;
    }
    __syncthreads();
#pragma unroll
    for (int t = 0; t < TTILE; t++) {
        float m = red_s[t * 16];
#pragma unroll
        for (int i = 1; i < 16; i++) m = fmaxf(m, red_s[t * 16 + i]);
        mx[t] = m;
    }
    __syncthreads();   // before reusing red_s

    float e[TTILE];
#pragma unroll
    for (int t = 0; t < TTILE; t++)
        e[t] = valid ? __expf(sc[t] - mx[t]) : 0.f;

#pragma unroll
    for (int t = 0; t < TTILE; t++) {
        float s = e[t];
#pragma unroll
        for (int o = 16; o > 0; o >>= 1) s += __shfl_xor_sync(0xffffffffu, s, o);
        if (lane == 0) red_s[t * 16 + wid] = s;
    }
    __syncthreads();

    float p[TTILE];
#pragma unroll
    for (int t = 0; t < TTILE; t++) {
        float s = 0.f;
#pragma unroll
        for (int i = 0; i < 16; i++) s += red_s[t * 16 + i];
        p[t] = e[t] * (1.0f / s);
    }

    // write align_vectors + stage p into smem (buf reuse: score phase done)
#pragma unroll
    for (int t = 0; t < TTILE; t++) {
        align_out[((size_t)(b * TT_ALL + t0 + t) << 9) + my_s] = p[t];
        buf[t * SS + my_s] = p[t];
    }
    __syncthreads();

    // ---- context: c[t,m] = sum_s p[t,s] * mems[b,s,m] ----
    const int m    = tid & 255;
    const int half = tid >> 8;
    float cacc[TTILE];
#pragma unroll
    for (int t = 0; t < TTILE; t++) cacc[t] = 0.f;

    const float* mb = mems + ((size_t)(b * SS + half * 256) << 8) + m;
#pragma unroll 4
    for (int s = 0; s < 256; s++) {
        const float mv = mb[(size_t)s << 8];
        const int sg = half * 256 + s;
#pragma unroll
        for (int t = 0; t < TTILE; t++)
            cacc[t] = fmaf(buf[t * SS + sg], mv, cacc[t]);
    }

    if (half == 1) {
#pragma unroll
        for (int t = 0; t < TTILE; t++) wq_s[t * MEM_DIM + m] = cacc[t];
    }
    __syncthreads();
    if (half == 0) {
#pragma unroll
        for (int t = 0; t < TTILE; t++)
            c_out[((size_t)(b * TT_ALL + t0 + t) << 8) + m] =
                cacc[t] + wq_s[t * MEM_DIM + m];
    }
}

// ---------------------------------------------------------------------------
// Launch
// ---------------------------------------------------------------------------
extern "C" void kernel_launch(void* const* d_in, const int* in_sizes, int n_in,
                              void* d_out, int out_size)
{
    const float* inputs    = (const float*)d_in[0];   // [B,T,512]
    const float* mems      = (const float*)d_in[1];   // [B,S,256]
    const int*   mem_masks = (const int*)  d_in[2];   // [B]
    const float* Wq        = (const float*)d_in[3];   // [256,512]
    const float* Wc        = (const float*)d_in[4];   // [256,256]
    const float* bc        = (const float*)d_in[5];   // [256]
    const float* v         = (const float*)d_in[6];   // [256]
    const float* Wout      = (const float*)d_in[7];   // [512,768]
    const float* bout      = (const float*)d_in[8];   // [512]

    float* out = (float*)d_out;
    float* attn_h    = out;                                   // [B,T,512]
    float* align_vec = out + (size_t)BB * TT_ALL * IN_DIM;    // [B,T,S]

    float *p_wq = nullptr, *p_uh = nullptr, *p_c = nullptr;
    cudaGetSymbolAddress((void**)&p_wq, g_wq);
    cudaGetSymbolAddress((void**)&p_uh, g_uh);
    cudaGetSymbolAddress((void**)&p_c,  g_c);

    const int M = BB * TT_ALL;   // 2048 rows (also B*S = 2048)

    // 1) wq = inputs @ Wq^T                 [2048,512] x [256,512]^T
    gemm_nt_kernel<<<dim3(MEM_DIM / 64, M / 64), 256>>>(
        inputs, nullptr, IN_DIM, Wq, nullptr, p_wq, M, MEM_DIM, IN_DIM);

    // 2) uh = mems @ Wc^T + bc              [2048,256] x [256,256]^T
    gemm_nt_kernel<<<dim3(MEM_DIM / 64, M / 64), 256>>>(
        mems, nullptr, MEM_DIM, Wc, bc, p_uh, M, MEM_DIM, MEM_DIM);

    // 3) fused tanh-score / softmax / context
    attn_core_kernel<<<dim3(TT_ALL / TTILE, BB), 512>>>(
        p_wq, p_uh, mems, mem_masks, v, align_vec, p_c);

    // 4) attn_h = [c, inputs] @ Wout^T + bout   [2048,768] x [512,768]^T
    gemm_nt_kernel<<<dim3(IN_DIM / 64, M / 64), 256>>>(
        p_c, inputs, MEM_DIM, Wout, bout, attn_h, M, IN_DIM, MEM_DIM + IN_DIM);
}

// round 3
// speedup vs baseline: 1.4934x; 1.4934x over previous
#include <cuda_runtime.h>
#include <cuda_bf16.h>
#include <cstdint>

// Problem constants
#define BB      4
#define TT_ALL  512
#define SS      512
#define IN_DIM  512
#define MEM_DIM 256

// Scratch (device globals; no allocations allowed)
__device__ __align__(16) float g_wq[BB * TT_ALL * MEM_DIM];   // [B,T,256]
__device__ __align__(16) float g_uh[BB * SS * MEM_DIM];       // [B,S,256]
__device__ __align__(16) float g_c [BB * TT_ALL * MEM_DIM];   // [B,T,256]

// ---------------------------------------------------------------------------
// TF32 tensor-core NT GEMM:  C[M,N] = Acat[M,K] * B[N,K]^T (+bias)
// Dual-A: rows with k < K1 come from A (pitch K1), k >= K1 from A2 (pitch K-K1).
// CTA tile 64x64, BK=32, 128 threads = 4 warps, warp tile 32x32.
// Requires M%64==0, N%64==0, K%32==0, K1%32==0.
// ---------------------------------------------------------------------------
#define GBM 64
#define GBN 64
#define GBK 32
#define SPITCH 36

__device__ __forceinline__ uint32_t f2tf32(float f) {
    uint32_t o;
    asm("cvt.rna.tf32.f32 %0, %1;" : "=r"(o) : "f"(f));
    return o;
}

__device__ __forceinline__ void mma_tf32(
    float& c0, float& c1, float& c2, float& c3,
    uint32_t a0, uint32_t a1, uint32_t a2, uint32_t a3,
    uint32_t b0, uint32_t b1)
{
    asm volatile(
        "mma.sync.aligned.m16n8k8.row.col.f32.tf32.tf32.f32 "
        "{%0,%1,%2,%3}, {%4,%5,%6,%7}, {%8,%9}, {%0,%1,%2,%3};\n"
        : "+f"(c0), "+f"(c1), "+f"(c2), "+f"(c3)
        : "r"(a0), "r"(a1), "r"(a2), "r"(a3), "r"(b0), "r"(b1));
}

__global__ __launch_bounds__(128) void gemm_tf32_kernel(
    const float* __restrict__ A, const float* __restrict__ A2, int K1,
    const float* __restrict__ Bm, const float* __restrict__ bias,
    float* __restrict__ C, int M, int N, int K)
{
    __shared__ float As[2][GBM][SPITCH];
    __shared__ float Bs[2][GBN][SPITCH];

    const int tid  = threadIdx.x;
    const int wid  = tid >> 5;
    const int lane = tid & 31;
    const int g    = lane >> 2;     // 0..7
    const int t    = lane & 3;      // 0..3
    const int wrow = (wid & 1) * 32;
    const int wcol = (wid >> 1) * 32;

    const int row0 = blockIdx.y * GBM;
    const int col0 = blockIdx.x * GBN;

    // staging indices
    const int srow = tid >> 3;          // 0..15
    const int sc4  = (tid & 7) * 4;     // 0..28 step 4

    const int K2 = K - K1;
    const int NP = K / GBK;

    float acc[2][4][4];
#pragma unroll
    for (int mt = 0; mt < 2; mt++)
#pragma unroll
        for (int nt = 0; nt < 4; nt++)
#pragma unroll
            for (int i = 0; i < 4; i++) acc[mt][nt][i] = 0.f;

    float4 ra[4], rb[4];

    // --- load panel 0 into regs ---
    {
        const float* srcA = A; int pitchA = K1; int kcolA = 0;
        if (A2 != nullptr && 0 >= K1) { srcA = A2; pitchA = K2; kcolA = -K1; }
#pragma unroll
        for (int i = 0; i < 4; i++) {
            ra[i] = *reinterpret_cast<const float4*>(
                srcA + (size_t)(row0 + srow + 16 * i) * pitchA + kcolA + sc4);
            rb[i] = *reinterpret_cast<const float4*>(
                Bm + (size_t)(col0 + srow + 16 * i) * K + 0 + sc4);
        }
        // store to buf 0 (with tf32 rounding)
#pragma unroll
        for (int i = 0; i < 4; i++) {
            float* pa = &As[0][srow + 16 * i][sc4];
            pa[0] = __uint_as_float(f2tf32(ra[i].x));
            pa[1] = __uint_as_float(f2tf32(ra[i].y));
            pa[2] = __uint_as_float(f2tf32(ra[i].z));
            pa[3] = __uint_as_float(f2tf32(ra[i].w));
            float* pb = &Bs[0][srow + 16 * i][sc4];
            pb[0] = __uint_as_float(f2tf32(rb[i].x));
            pb[1] = __uint_as_float(f2tf32(rb[i].y));
            pb[2] = __uint_as_float(f2tf32(rb[i].z));
            pb[3] = __uint_as_float(f2tf32(rb[i].w));
        }
    }
    __syncthreads();

    for (int p = 0; p < NP; p++) {
        // prefetch next panel into regs
        if (p + 1 < NP) {
            const int k0 = (p + 1) * GBK;
            const float* srcA = A; int pitchA = K1; int kcolA = k0;
            if (A2 != nullptr && k0 >= K1) { srcA = A2; pitchA = K2; kcolA = k0 - K1; }
#pragma unroll
            for (int i = 0; i < 4; i++) {
                ra[i] = *reinterpret_cast<const float4*>(
                    srcA + (size_t)(row0 + srow + 16 * i) * pitchA + kcolA + sc4);
                rb[i] = *reinterpret_cast<const float4*>(
                    Bm + (size_t)(col0 + srow + 16 * i) * K + k0 + sc4);
            }
        }

        // compute on buffer p&1
        const float* ab = &As[p & 1][0][0];
        const float* bb = &Bs[p & 1][0][0];
#pragma unroll
        for (int kk = 0; kk < GBK; kk += 8) {
            uint32_t af[2][4], bf[4][2];
#pragma unroll
            for (int mt = 0; mt < 2; mt++) {
                const int r = wrow + 16 * mt + g;
                af[mt][0] = __float_as_uint(ab[(r)     * SPITCH + kk + t]);
                af[mt][1] = __float_as_uint(ab[(r + 8) * SPITCH + kk + t]);
                af[mt][2] = __float_as_uint(ab[(r)     * SPITCH + kk + t + 4]);
                af[mt][3] = __float_as_uint(ab[(r + 8) * SPITCH + kk + t + 4]);
            }
#pragma unroll
            for (int nt = 0; nt < 4; nt++) {
                const int n = wcol + 8 * nt + g;
                bf[nt][0] = __float_as_uint(bb[n * SPITCH + kk + t]);
                bf[nt][1] = __float_as_uint(bb[n * SPITCH + kk + t + 4]);
            }
#pragma unroll
            for (int mt = 0; mt < 2; mt++)
#pragma unroll
                for (int nt = 0; nt < 4; nt++)
                    mma_tf32(acc[mt][nt][0], acc[mt][nt][1],
                             acc[mt][nt][2], acc[mt][nt][3],
                             af[mt][0], af[mt][1], af[mt][2], af[mt][3],
                             bf[nt][0], bf[nt][1]);
        }

        // store prefetched panel to the other buffer
        if (p + 1 < NP) {
            const int nb = (p + 1) & 1;
#pragma unroll
            for (int i = 0; i < 4; i++) {
                float* pa = &As[nb][srow + 16 * i][sc4];
                pa[0] = __uint_as_float(f2tf32(ra[i].x));
                pa[1] = __uint_as_float(f2tf32(ra[i].y));
                pa[2] = __uint_as_float(f2tf32(ra[i].z));
                pa[3] = __uint_as_float(f2tf32(ra[i].w));
                float* pb = &Bs[nb][srow + 16 * i][sc4];
                pb[0] = __uint_as_float(f2tf32(rb[i].x));
                pb[1] = __uint_as_float(f2tf32(rb[i].y));
                pb[2] = __uint_as_float(f2tf32(rb[i].z));
                pb[3] = __uint_as_float(f2tf32(rb[i].w));
            }
        }
        __syncthreads();
    }

    // epilogue
#pragma unroll
    for (int mt = 0; mt < 2; mt++) {
        const int row = row0 + wrow + 16 * mt + g;
#pragma unroll
        for (int nt = 0; nt < 4; nt++) {
            const int col = col0 + wcol + 8 * nt + 2 * t;
            float b0v = 0.f, b1v = 0.f;
            if (bias != nullptr) { b0v = bias[col]; b1v = bias[col + 1]; }
            C[(size_t)row * N + col]           = acc[mt][nt][0] + b0v;
            C[(size_t)row * N + col + 1]       = acc[mt][nt][1] + b1v;
            C[(size_t)(row + 8) * N + col]     = acc[mt][nt][2] + b0v;
            C[(size_t)(row + 8) * N + col + 1] = acc[mt][nt][3] + b1v;
        }
    }
}

// ---------------------------------------------------------------------------
// Fused attention core: scores -> tanh -> dot(v) -> masked softmax -> context
// Grid: (T/TTILE, B), 512 threads. Thread owns one s.
// ---------------------------------------------------------------------------
#define TTILE 8
#define DTILE 16
#define UH_PITCH 514   // conflict-free transpose store + read

__device__ __forceinline__ float tanh_fast(float x) {
    float y;
    asm("tanh.approx.f32 %0, %1;" : "=f"(y) : "f"(x));
    return y;
}

__global__ __launch_bounds__(512) void attn_core_kernel(
    const float* __restrict__ wq,        // [B,T,256]
    const float* __restrict__ uh,        // [B,S,256]
    const float* __restrict__ mems,      // [B,S,256]
    const int*   __restrict__ mem_masks, // [B]
    const float* __restrict__ v,         // [256]
    float* __restrict__ align_out,       // [B,T,S]
    float* __restrict__ c_out)           // [B,T,256]
{
    __shared__ float wq_s[TTILE * MEM_DIM];       // 8 KB (reused as c_part)
    __shared__ float v_s[MEM_DIM];                // 1 KB
    __shared__ float buf[DTILE * UH_PITCH];       // 32.1 KB: uh tile, then p
    __shared__ float red_s[TTILE * 16];           // block reduce

    const int tid = threadIdx.x;
    const int b  = blockIdx.y;
    const int t0 = blockIdx.x * TTILE;
    const int my_s = tid;
    const int lane = tid & 31;
    const int wid  = tid >> 5;

    // stage wq rows + v
    for (int i = tid; i < TTILE * MEM_DIM; i += 512)
        wq_s[i] = wq[((size_t)(b * TT_ALL + t0 + (i >> 8)) << 8) + (i & 255)];
    for (int i = tid; i < MEM_DIM; i += 512)
        v_s[i] = v[i];

    const int mlen = mem_masks[b];

    float acc[TTILE];
#pragma unroll
    for (int t = 0; t < TTILE; t++) acc[t] = 0.f;

    // ---- score phase: acc[t] = sum_d tanh(wq[t,d] + uh[s,d]) * v[d] ----
    for (int d0 = 0; d0 < MEM_DIM; d0 += DTILE) {
        __syncthreads();
        // load uh[b, :, d0:d0+16] transposed into buf[dl][s]
#pragma unroll
        for (int it = 0; it < 4; it++) {
            const int s = (tid >> 2) + it * 128;
            const int c = tid & 3;
            float4 u4 = *reinterpret_cast<const float4*>(
                uh + ((size_t)(b * SS + s) << 8) + d0 + c * 4);
            buf[(c * 4 + 0) * UH_PITCH + s] = u4.x;
            buf[(c * 4 + 1) * UH_PITCH + s] = u4.y;
            buf[(c * 4 + 2) * UH_PITCH + s] = u4.z;
            buf[(c * 4 + 3) * UH_PITCH + s] = u4.w;
        }
        __syncthreads();

#pragma unroll
        for (int dl = 0; dl < DTILE; dl++) {
            const float u  = buf[dl * UH_PITCH + my_s];
            const float vv = v_s[d0 + dl];
#pragma unroll
            for (int t = 0; t < TTILE; t++) {
                const float x = wq_s[t * MEM_DIM + d0 + dl] + u;
                acc[t] = fmaf(tanh_fast(x), vv, acc[t]);
            }
        }
    }

    // ---- masked softmax over s (512 threads) ----
    const bool valid = (my_s < mlen);
    float sc[TTILE];
#pragma unroll
    for (int t = 0; t < TTILE; t++) sc[t] = valid ? acc[t] : -1e30f;

    float mx[TTILE];
#pragma unroll
    for (int t = 0; t < TTILE; t++) {
        float m = sc[t];
#pragma unroll
        for (int o = 16; o > 0; o >>= 1) m = fmaxf(m, __shfl_xor_sync(0xffffffffu, m, o));
        if (lane == 0) red_s[t * 16 + wid] = m;
    }
    __syncthreads();
#pragma unroll
    for (int t = 0; t < TTILE; t++) {
        float m = red_s[t * 16];
#pragma unroll
        for (int i = 1; i < 16; i++) m = fmaxf(m, red_s[t * 16 + i]);
        mx[t] = m;
    }
    __syncthreads();   // before reusing red_s

    float e[TTILE];
#pragma unroll
    for (int t = 0; t < TTILE; t++)
        e[t] = valid ? __expf(sc[t] - mx[t]) : 0.f;

#pragma unroll
    for (int t = 0; t < TTILE; t++) {
        float s = e[t];
#pragma unroll
        for (int o = 16; o > 0; o >>= 1) s += __shfl_xor_sync(0xffffffffu, s, o);
        if (lane == 0) red_s[t * 16 + wid] = s;
    }
    __syncthreads();

    float p[TTILE];
#pragma unroll
    for (int t = 0; t < TTILE; t++) {
        float s = 0.f;
#pragma unroll
        for (int i = 0; i < 16; i++) s += red_s[t * 16 + i];
        p[t] = e[t] * (1.0f / s);
    }

    // write align_vectors + stage p into smem (buf reuse: score phase done)
#pragma unroll
    for (int t = 0; t < TTILE; t++) {
        align_out[((size_t)(b * TT_ALL + t0 + t) << 9) + my_s] = p[t];
        buf[t * SS + my_s] = p[t];
    }
    __syncthreads();

    // ---- context: c[t,m] = sum_s p[t,s] * mems[b,s,m] ----
    const int m    = tid & 255;
    const int half = tid >> 8;
    float cacc[TTILE];
#pragma unroll
    for (int t = 0; t < TTILE; t++) cacc[t] = 0.f;

    const float* mb = mems + ((size_t)(b * SS + half * 256) << 8) + m;
#pragma unroll 4
    for (int s = 0; s < 256; s++) {
        const float mv = mb[(size_t)s << 8];
        const int sg = half * 256 + s;
#pragma unroll
        for (int t = 0; t < TTILE; t++)
            cacc[t] = fmaf(buf[t * SS + sg], mv, cacc[t]);
    }

    if (half == 1) {
#pragma unroll
        for (int t = 0; t < TTILE; t++) wq_s[t * MEM_DIM + m] = cacc[t];
    }
    __syncthreads();
    if (half == 0) {
#pragma unroll
        for (int t = 0; t < TTILE; t++)
            c_out[((size_t)(b * TT_ALL + t0 + t) << 8) + m] =
                cacc[t] + wq_s[t * MEM_DIM + m];
    }
}

// ---------------------------------------------------------------------------
// Launch
// ---------------------------------------------------------------------------
extern "C" void kernel_launch(void* const* d_in, const int* in_sizes, int n_in,
                              void* d_out, int out_size)
{
    const float* inputs    = (const float*)d_in[0];   // [B,T,512]
    const float* mems      = (const float*)d_in[1];   // [B,S,256]
    const int*   mem_masks = (const int*)  d_in[2];   // [B]
    const float* Wq        = (const float*)d_in[3];   // [256,512]
    const float* Wc        = (const float*)d_in[4];   // [256,256]
    const float* bc        = (const float*)d_in[5];   // [256]
    const float* v         = (const float*)d_in[6];   // [256]
    const float* Wout      = (const float*)d_in[7];   // [512,768]
    const float* bout      = (const float*)d_in[8];   // [512]

    float* out = (float*)d_out;
    float* attn_h    = out;                                   // [B,T,512]
    float* align_vec = out + (size_t)BB * TT_ALL * IN_DIM;    // [B,T,S]

    float *p_wq = nullptr, *p_uh = nullptr, *p_c = nullptr;
    cudaGetSymbolAddress((void**)&p_wq, g_wq);
    cudaGetSymbolAddress((void**)&p_uh, g_uh);
    cudaGetSymbolAddress((void**)&p_c,  g_c);

    const int M = BB * TT_ALL;   // 2048 rows (also B*S = 2048)

    // 1) wq = inputs @ Wq^T                 [2048,512] x [256,512]^T
    gemm_tf32_kernel<<<dim3(MEM_DIM / GBN, M / GBM), 128>>>(
        inputs, nullptr, IN_DIM, Wq, nullptr, p_wq, M, MEM_DIM, IN_DIM);

    // 2) uh = mems @ Wc^T + bc              [2048,256] x [256,256]^T
    gemm_tf32_kernel<<<dim3(MEM_DIM / GBN, M / GBM), 128>>>(
        mems, nullptr, MEM_DIM, Wc, bc, p_uh, M, MEM_DIM, MEM_DIM);

    // 3) fused tanh-score / softmax / context
    attn_core_kernel<<<dim3(TT_ALL / TTILE, BB), 512>>>(
        p_wq, p_uh, mems, mem_masks, v, align_vec, p_c);

    // 4) attn_h = [c, inputs] @ Wout^T + bout   [2048,768] x [512,768]^T
    gemm_tf32_kernel<<<dim3(IN_DIM / GBN, M / GBM), 128>>>(
        p_c, inputs, MEM_DIM, Wout, bout, attn_h, M, IN_DIM, MEM_DIM + IN_DIM);
}

// round 4
// speedup vs baseline: 1.5932x; 1.0668x over previous
#include <cuda_runtime.h>
#include <cuda_bf16.h>
#include <cstdint>

// Problem constants
#define BB      4
#define TT_ALL  512
#define SS      512
#define IN_DIM  512
#define MEM_DIM 256

// Scratch (device globals; no allocations allowed)
__device__ __align__(16) float g_wq[BB * TT_ALL * MEM_DIM];   // [B,T,256]
__device__ __align__(16) float g_uh[BB * SS * MEM_DIM];       // [B,S,256]
__device__ __align__(16) float g_c [BB * TT_ALL * MEM_DIM];   // [B,T,256]

// ---------------------------------------------------------------------------
// TF32 tensor-core NT GEMM body:  C[M,N] tile = Acat[M,K] * B[N,K]^T (+bias)
// Dual-A: rows with k < K1 come from A (pitch K1), k >= K1 from A2 (pitch K-K1).
// CTA tile 64x64, BK=32, 128 threads = 4 warps, warp tile 32x32.
// ---------------------------------------------------------------------------
#define GBM 64
#define GBN 64
#define GBK 32
#define SPITCH 36

__device__ __forceinline__ uint32_t f2tf32(float f) {
    uint32_t o;
    asm("cvt.rna.tf32.f32 %0, %1;" : "=r"(o) : "f"(f));
    return o;
}

__device__ __forceinline__ void mma_tf32(
    float& c0, float& c1, float& c2, float& c3,
    uint32_t a0, uint32_t a1, uint32_t a2, uint32_t a3,
    uint32_t b0, uint32_t b1)
{
    asm volatile(
        "mma.sync.aligned.m16n8k8.row.col.f32.tf32.tf32.f32 "
        "{%0,%1,%2,%3}, {%4,%5,%6,%7}, {%8,%9}, {%0,%1,%2,%3};\n"
        : "+f"(c0), "+f"(c1), "+f"(c2), "+f"(c3)
        : "r"(a0), "r"(a1), "r"(a2), "r"(a3), "r"(b0), "r"(b1));
}

struct GemmSmem {
    float As[2][GBM][SPITCH];
    float Bs[2][GBN][SPITCH];
};

__device__ __forceinline__ void gemm_body(
    GemmSmem* sm,
    const float* __restrict__ A, const float* __restrict__ A2, int K1,
    const float* __restrict__ Bm, const float* __restrict__ bias,
    float* __restrict__ C, int N, int K, int row0, int col0)
{
    const int tid  = threadIdx.x;
    const int wid  = tid >> 5;
    const int lane = tid & 31;
    const int g    = lane >> 2;     // 0..7
    const int t    = lane & 3;      // 0..3
    const int wrow = (wid & 1) * 32;
    const int wcol = (wid >> 1) * 32;

    // staging indices
    const int srow = tid >> 3;          // 0..15
    const int sc4  = (tid & 7) * 4;     // 0..28 step 4

    const int K2 = K - K1;
    const int NP = K / GBK;

    float acc[2][4][4];
#pragma unroll
    for (int mt = 0; mt < 2; mt++)
#pragma unroll
        for (int nt = 0; nt < 4; nt++)
#pragma unroll
            for (int i = 0; i < 4; i++) acc[mt][nt][i] = 0.f;

    float4 ra[4], rb[4];

    // --- load panel 0 into regs, store to buf 0 ---
    {
        const float* srcA = A; int pitchA = K1; int kcolA = 0;
#pragma unroll
        for (int i = 0; i < 4; i++) {
            ra[i] = *reinterpret_cast<const float4*>(
                srcA + (size_t)(row0 + srow + 16 * i) * pitchA + kcolA + sc4);
            rb[i] = *reinterpret_cast<const float4*>(
                Bm + (size_t)(col0 + srow + 16 * i) * K + sc4);
        }
#pragma unroll
        for (int i = 0; i < 4; i++) {
            float* pa = &sm->As[0][srow + 16 * i][sc4];
            pa[0] = __uint_as_float(f2tf32(ra[i].x));
            pa[1] = __uint_as_float(f2tf32(ra[i].y));
            pa[2] = __uint_as_float(f2tf32(ra[i].z));
            pa[3] = __uint_as_float(f2tf32(ra[i].w));
            float* pb = &sm->Bs[0][srow + 16 * i][sc4];
            pb[0] = __uint_as_float(f2tf32(rb[i].x));
            pb[1] = __uint_as_float(f2tf32(rb[i].y));
            pb[2] = __uint_as_float(f2tf32(rb[i].z));
            pb[3] = __uint_as_float(f2tf32(rb[i].w));
        }
    }
    __syncthreads();

    for (int p = 0; p < NP; p++) {
        // prefetch next panel into regs
        if (p + 1 < NP) {
            const int k0 = (p + 1) * GBK;
            const float* srcA = A; int pitchA = K1; int kcolA = k0;
            if (A2 != nullptr && k0 >= K1) { srcA = A2; pitchA = K2; kcolA = k0 - K1; }
#pragma unroll
            for (int i = 0; i < 4; i++) {
                ra[i] = *reinterpret_cast<const float4*>(
                    srcA + (size_t)(row0 + srow + 16 * i) * pitchA + kcolA + sc4);
                rb[i] = *reinterpret_cast<const float4*>(
                    Bm + (size_t)(col0 + srow + 16 * i) * K + k0 + sc4);
            }
        }

        // compute on buffer p&1
        const float* ab = &sm->As[p & 1][0][0];
        const float* bb = &sm->Bs[p & 1][0][0];
#pragma unroll
        for (int kk = 0; kk < GBK; kk += 8) {
            uint32_t af[2][4], bf[4][2];
#pragma unroll
            for (int mt = 0; mt < 2; mt++) {
                const int r = wrow + 16 * mt + g;
                af[mt][0] = __float_as_uint(ab[(r)     * SPITCH + kk + t]);
                af[mt][1] = __float_as_uint(ab[(r + 8) * SPITCH + kk + t]);
                af[mt][2] = __float_as_uint(ab[(r)     * SPITCH + kk + t + 4]);
                af[mt][3] = __float_as_uint(ab[(r + 8) * SPITCH + kk + t + 4]);
            }
#pragma unroll
            for (int nt = 0; nt < 4; nt++) {
                const int n = wcol + 8 * nt + g;
                bf[nt][0] = __float_as_uint(bb[n * SPITCH + kk + t]);
                bf[nt][1] = __float_as_uint(bb[n * SPITCH + kk + t + 4]);
            }
#pragma unroll
            for (int mt = 0; mt < 2; mt++)
#pragma unroll
                for (int nt = 0; nt < 4; nt++)
                    mma_tf32(acc[mt][nt][0], acc[mt][nt][1],
                             acc[mt][nt][2], acc[mt][nt][3],
                             af[mt][0], af[mt][1], af[mt][2], af[mt][3],
                             bf[nt][0], bf[nt][1]);
        }

        // store prefetched panel to the other buffer
        if (p + 1 < NP) {
            const int nb = (p + 1) & 1;
#pragma unroll
            for (int i = 0; i < 4; i++) {
                float* pa = &sm->As[nb][srow + 16 * i][sc4];
                pa[0] = __uint_as_float(f2tf32(ra[i].x));
                pa[1] = __uint_as_float(f2tf32(ra[i].y));
                pa[2] = __uint_as_float(f2tf32(ra[i].z));
                pa[3] = __uint_as_float(f2tf32(ra[i].w));
                float* pb = &sm->Bs[nb][srow + 16 * i][sc4];
                pb[0] = __uint_as_float(f2tf32(rb[i].x));
                pb[1] = __uint_as_float(f2tf32(rb[i].y));
                pb[2] = __uint_as_float(f2tf32(rb[i].z));
                pb[3] = __uint_as_float(f2tf32(rb[i].w));
            }
        }
        __syncthreads();
    }

    // epilogue
#pragma unroll
    for (int mt = 0; mt < 2; mt++) {
        const int row = row0 + wrow + 16 * mt + g;
#pragma unroll
        for (int nt = 0; nt < 4; nt++) {
            const int col = col0 + wcol + 8 * nt + 2 * t;
            float b0v = 0.f, b1v = 0.f;
            if (bias != nullptr) { b0v = bias[col]; b1v = bias[col + 1]; }
            C[(size_t)row * N + col]           = acc[mt][nt][0] + b0v;
            C[(size_t)row * N + col + 1]       = acc[mt][nt][1] + b1v;
            C[(size_t)(row + 8) * N + col]     = acc[mt][nt][2] + b0v;
            C[(size_t)(row + 8) * N + col + 1] = acc[mt][nt][3] + b1v;
        }
    }
}

// merged k1+k2: grid (4, 64). by<32 -> wq GEMM, else uh GEMM.
__global__ __launch_bounds__(128) void gemm_k1k2_kernel(
    const float* __restrict__ inputs, const float* __restrict__ Wq,
    const float* __restrict__ mems,   const float* __restrict__ Wc,
    const float* __restrict__ bc,
    float* __restrict__ owq, float* __restrict__ ouh)
{
    __shared__ GemmSmem sm;
    const int bx = blockIdx.x, by = blockIdx.y;
    if (by < 32) {
        gemm_body(&sm, inputs, nullptr, IN_DIM, Wq, nullptr, owq,
                  MEM_DIM, IN_DIM, by * GBM, bx * GBN);
    } else {
        gemm_body(&sm, mems, nullptr, MEM_DIM, Wc, bc, ouh,
                  MEM_DIM, MEM_DIM, (by - 32) * GBM, bx * GBN);
    }
}

// k4: dual-A output projection
__global__ __launch_bounds__(128) void gemm_out_kernel(
    const float* __restrict__ Cmat, const float* __restrict__ inputs,
    const float* __restrict__ Wout, const float* __restrict__ bout,
    float* __restrict__ attn_h)
{
    __shared__ GemmSmem sm;
    gemm_body(&sm, Cmat, inputs, MEM_DIM, Wout, bout, attn_h,
              IN_DIM, MEM_DIM + IN_DIM, blockIdx.y * GBM, blockIdx.x * GBN);
}

// ---------------------------------------------------------------------------
// Fused attention core: scores -> tanh -> dot(v) -> masked softmax -> context
// Grid: (T/TTILE, B), 512 threads. Thread owns one s.
// cp.async double-buffered uh tiles, s-major pitch-20 layout.
// ---------------------------------------------------------------------------
#define TTILE 8
#define DTILE 16
#define UPITCH 20
#define UBUF_ELEMS (SS * UPITCH)          // 10240 floats per buffer
#define ATTN_SMEM_FLOATS (2 * UBUF_ELEMS + TTILE * MEM_DIM + MEM_DIM + TTILE * 16)
#define ATTN_SMEM_BYTES  (ATTN_SMEM_FLOATS * 4)

__device__ __forceinline__ float tanh_fast(float x) {
    float y;
    asm("tanh.approx.f32 %0, %1;" : "=f"(y) : "f"(x));
    return y;
}

__device__ __forceinline__ void cp_async16(void* sdst, const void* gsrc) {
    uint32_t sa = (uint32_t)__cvta_generic_to_shared(sdst);
    asm volatile("cp.async.ca.shared.global [%0], [%1], 16;\n" :: "r"(sa), "l"(gsrc));
}
#define CP_COMMIT()  asm volatile("cp.async.commit_group;\n")
#define CP_WAIT(N)   asm volatile("cp.async.wait_group %0;\n" :: "n"(N))

__device__ __forceinline__ void prefetch_uh(
    const float* __restrict__ uh_b, float* ubuf, int d0, int tid)
{
    const int c  = tid & 3;
    const int s0 = tid >> 2;
#pragma unroll
    for (int it = 0; it < 4; it++) {
        const int s = s0 + it * 128;
        cp_async16(ubuf + s * UPITCH + c * 4,
                   uh_b + ((size_t)s << 8) + d0 + c * 4);
    }
}

__global__ __launch_bounds__(512) void attn_core_kernel(
    const float* __restrict__ wq,        // [B,T,256]
    const float* __restrict__ uh,        // [B,S,256]
    const float* __restrict__ mems,      // [B,S,256]
    const int*   __restrict__ mem_masks, // [B]
    const float* __restrict__ v,         // [256]
    float* __restrict__ align_out,       // [B,T,S]
    float* __restrict__ c_out)           // [B,T,256]
{
    extern __shared__ float sdyn[];
    float* ubuf0 = sdyn;                          // [512][20]
    float* ubuf1 = sdyn + UBUF_ELEMS;             // [512][20]
    float* wq_s  = sdyn + 2 * UBUF_ELEMS;         // [8][256]
    float* v_s   = wq_s + TTILE * MEM_DIM;        // [256]
    float* red_s = v_s + MEM_DIM;                 // [8][16]
    float* pbuf  = ubuf0;                         // reused for p: [8][512]

    const int tid  = threadIdx.x;
    const int b    = blockIdx.y;
    const int t0   = blockIdx.x * TTILE;
    const int my_s = tid;
    const int lane = tid & 31;
    const int wid  = tid >> 5;

    const float* uh_b = uh + ((size_t)b * SS << 8);

    // stage wq rows (512 float4 = exactly 1 per thread) + v
    {
        const int t  = tid >> 6;
        const int c4 = (tid & 63) * 4;
        *reinterpret_cast<float4*>(wq_s + t * MEM_DIM + c4) =
            *reinterpret_cast<const float4*>(
                wq + ((size_t)(b * TT_ALL + t0 + t) << 8) + c4);
        if (tid < 64)
            *reinterpret_cast<float4*>(v_s + tid * 4) =
                *reinterpret_cast<const float4*>(v + tid * 4);
    }

    const int mlen = mem_masks[b];

    float acc[TTILE];
#pragma unroll
    for (int t = 0; t < TTILE; t++) acc[t] = 0.f;

    // ---- score phase with cp.async double buffering ----
    prefetch_uh(uh_b, ubuf0, 0, tid);
    CP_COMMIT();

#pragma unroll 1
    for (int tile = 0; tile < MEM_DIM / DTILE; tile++) {
        const int d0 = tile * DTILE;
        if (tile + 1 < MEM_DIM / DTILE) {
            prefetch_uh(uh_b, (tile & 1) ? ubuf0 : ubuf1, d0 + DTILE, tid);
            CP_COMMIT();
            CP_WAIT(1);
        } else {
            CP_WAIT(0);
        }
        __syncthreads();

        const float* ub = ((tile & 1) ? ubuf1 : ubuf0) + my_s * UPITCH;
#pragma unroll
        for (int q = 0; q < 4; q++) {
            const float4 u4 = *reinterpret_cast<const float4*>(ub + q * 4);
            const float4 v4 = *reinterpret_cast<const float4*>(v_s + d0 + q * 4);
#pragma unroll
            for (int t = 0; t < TTILE; t++) {
                const float4 w4 = *reinterpret_cast<const float4*>(
                    wq_s + t * MEM_DIM + d0 + q * 4);
                float a = acc[t];
                a = fmaf(tanh_fast(w4.x + u4.x), v4.x, a);
                a = fmaf(tanh_fast(w4.y + u4.y), v4.y, a);
                a = fmaf(tanh_fast(w4.z + u4.z), v4.z, a);
                a = fmaf(tanh_fast(w4.w + u4.w), v4.w, a);
                acc[t] = a;
            }
        }
        __syncthreads();
    }

    // ---- masked softmax over s (512 threads) ----
    const bool valid = (my_s < mlen);
    float sc[TTILE];
#pragma unroll
    for (int t = 0; t < TTILE; t++) sc[t] = valid ? acc[t] : -1e30f;

    float mx[TTILE];
#pragma unroll
    for (int t = 0; t < TTILE; t++) {
        float m = sc[t];
#pragma unroll
        for (int o = 16; o > 0; o >>= 1) m = fmaxf(m, __shfl_xor_sync(0xffffffffu, m, o));
        if (lane == 0) red_s[t * 16 + wid] = m;
    }
    __syncthreads();
#pragma unroll
    for (int t = 0; t < TTILE; t++) {
        float m = red_s[t * 16];
#pragma unroll
        for (int i = 1; i < 16; i++) m = fmaxf(m, red_s[t * 16 + i]);
        mx[t] = m;
    }
    __syncthreads();   // before reusing red_s

    float e[TTILE];
#pragma unroll
    for (int t = 0; t < TTILE; t++)
        e[t] = valid ? __expf(sc[t] - mx[t]) : 0.f;

#pragma unroll
    for (int t = 0; t < TTILE; t++) {
        float s = e[t];
#pragma unroll
        for (int o = 16; o > 0; o >>= 1) s += __shfl_xor_sync(0xffffffffu, s, o);
        if (lane == 0) red_s[t * 16 + wid] = s;
    }
    __syncthreads();

    float p[TTILE];
#pragma unroll
    for (int t = 0; t < TTILE; t++) {
        float s = 0.f;
#pragma unroll
        for (int i = 0; i < 16; i++) s += red_s[t * 16 + i];
        p[t] = e[t] * (1.0f / s);
    }

    // write align_vectors + stage p into smem (pbuf reuses ubuf0)
#pragma unroll
    for (int t = 0; t < TTILE; t++) {
        align_out[((size_t)(b * TT_ALL + t0 + t) << 9) + my_s] = p[t];
        pbuf[t * SS + my_s] = p[t];
    }
    __syncthreads();

    // ---- context: c[t,m] = sum_s p[t,s] * mems[b,s,m] ----
    const int m    = tid & 255;
    const int half = tid >> 8;
    float cacc[TTILE];
#pragma unroll
    for (int t = 0; t < TTILE; t++) cacc[t] = 0.f;

    const float* mb = mems + ((size_t)(b * SS + half * 256) << 8) + m;
    const float* pb = pbuf + half * 256;
#pragma unroll 2
    for (int s4 = 0; s4 < 64; s4++) {
        const float mv0 = mb[(size_t)(s4 * 4 + 0) << 8];
        const float mv1 = mb[(size_t)(s4 * 4 + 1) << 8];
        const float mv2 = mb[(size_t)(s4 * 4 + 2) << 8];
        const float mv3 = mb[(size_t)(s4 * 4 + 3) << 8];
#pragma unroll
        for (int t = 0; t < TTILE; t++) {
            const float4 pv = *reinterpret_cast<const float4*>(pb + t * SS + s4 * 4);
            cacc[t] = fmaf(pv.x, mv0,
                      fmaf(pv.y, mv1,
                      fmaf(pv.z, mv2,
                      fmaf(pv.w, mv3, cacc[t]))));
        }
    }

    if (half == 1) {
#pragma unroll
        for (int t = 0; t < TTILE; t++) wq_s[t * MEM_DIM + m] = cacc[t];
    }
    __syncthreads();
    if (half == 0) {
#pragma unroll
        for (int t = 0; t < TTILE; t++)
            c_out[((size_t)(b * TT_ALL + t0 + t) << 8) + m] =
                cacc[t] + wq_s[t * MEM_DIM + m];
    }
}

// ---------------------------------------------------------------------------
// Launch
// ---------------------------------------------------------------------------
extern "C" void kernel_launch(void* const* d_in, const int* in_sizes, int n_in,
                              void* d_out, int out_size)
{
    const float* inputs    = (const float*)d_in[0];   // [B,T,512]
    const float* mems      = (const float*)d_in[1];   // [B,S,256]
    const int*   mem_masks = (const int*)  d_in[2];   // [B]
    const float* Wq        = (const float*)d_in[3];   // [256,512]
    const float* Wc        = (const float*)d_in[4];   // [256,256]
    const float* bc        = (const float*)d_in[5];   // [256]
    const float* v         = (const float*)d_in[6];   // [256]
    const float* Wout      = (const float*)d_in[7];   // [512,768]
    const float* bout      = (const float*)d_in[8];   // [512]

    float* out = (float*)d_out;
    float* attn_h    = out;                                   // [B,T,512]
    float* align_vec = out + (size_t)BB * TT_ALL * IN_DIM;    // [B,T,S]

    float *p_wq = nullptr, *p_uh = nullptr, *p_c = nullptr;
    cudaGetSymbolAddress((void**)&p_wq, g_wq);
    cudaGetSymbolAddress((void**)&p_uh, g_uh);
    cudaGetSymbolAddress((void**)&p_c,  g_c);

    static bool attr_set = false;
    if (!attr_set) {
        cudaFuncSetAttribute(attn_core_kernel,
                             cudaFuncAttributeMaxDynamicSharedMemorySize,
                             ATTN_SMEM_BYTES);
        attr_set = true;
    }

    // 1+2) merged wq / uh GEMMs
    gemm_k1k2_kernel<<<dim3(MEM_DIM / GBN, 64), 128>>>(
        inputs, Wq, mems, Wc, bc, p_wq, p_uh);

    // 3) fused tanh-score / softmax / context
    attn_core_kernel<<<dim3(TT_ALL / TTILE, BB), 512, ATTN_SMEM_BYTES>>>(
        p_wq, p_uh, mems, mem_masks, v, align_vec, p_c);

    // 4) attn_h = [c, inputs] @ Wout^T + bout
    gemm_out_kernel<<<dim3(IN_DIM / GBN, (BB * TT_ALL) / GBM), 128>>>(
        p_c, inputs, Wout, bout, attn_h);
}

// round 6
// speedup vs baseline: 1.6706x; 1.0486x over previous
#include <cuda_runtime.h>
#include <cuda_bf16.h>
#include <cstdint>

// Problem constants
#define BB      4
#define TT_ALL  512
#define SS      512
#define IN_DIM  512
#define MEM_DIM 256

// Scratch (device globals; no allocations allowed)
__device__ __align__(16) float g_wq[BB * TT_ALL * MEM_DIM];   // [B,T,256]
__device__ __align__(16) float g_uh[BB * SS * MEM_DIM];       // [B,S,256]
__device__ __align__(16) float g_c [BB * TT_ALL * MEM_DIM];   // [B,T,256]

// ---------------------------------------------------------------------------
// TF32 tensor-core NT GEMM body:  C tile = Acat[M,K] * B[N,K]^T (+bias)
// Dual-A: rows with k < K1 come from A (pitch K1), k >= K1 from A2 (pitch K-K1).
// CTA tile 128x64, BK=32, 256 threads = 8 warps (4m x 2n), warp tile 32x32.
// Shared memory is DYNAMIC (55.3 KB > 48 KB static limit).
// ---------------------------------------------------------------------------
#define GBM 128
#define GBN 64
#define GBK 32
#define SPITCH 36

__device__ __forceinline__ uint32_t f2tf32(float f) {
    uint32_t o;
    asm("cvt.rna.tf32.f32 %0, %1;" : "=r"(o) : "f"(f));
    return o;
}

__device__ __forceinline__ void mma_tf32(
    float& c0, float& c1, float& c2, float& c3,
    uint32_t a0, uint32_t a1, uint32_t a2, uint32_t a3,
    uint32_t b0, uint32_t b1)
{
    asm volatile(
        "mma.sync.aligned.m16n8k8.row.col.f32.tf32.tf32.f32 "
        "{%0,%1,%2,%3}, {%4,%5,%6,%7}, {%8,%9}, {%0,%1,%2,%3};\n"
        : "+f"(c0), "+f"(c1), "+f"(c2), "+f"(c3)
        : "r"(a0), "r"(a1), "r"(a2), "r"(a3), "r"(b0), "r"(b1));
}

struct GemmSmem {
    float As[2][GBM][SPITCH];   // 36 KB
    float Bs[2][GBN][SPITCH];   // 18 KB
};
#define GEMM_SMEM_BYTES ((int)sizeof(GemmSmem))

__device__ __forceinline__ void store_tf32_4(float* p, float4 v) {
    p[0] = __uint_as_float(f2tf32(v.x));
    p[1] = __uint_as_float(f2tf32(v.y));
    p[2] = __uint_as_float(f2tf32(v.z));
    p[3] = __uint_as_float(f2tf32(v.w));
}

__device__ __forceinline__ void gemm_body(
    GemmSmem* sm,
    const float* __restrict__ A, const float* __restrict__ A2, int K1,
    const float* __restrict__ Bm, const float* __restrict__ bias,
    float* __restrict__ C, int N, int K, int row0, int col0)
{
    const int tid  = threadIdx.x;
    const int wid  = tid >> 5;
    const int lane = tid & 31;
    const int g    = lane >> 2;     // 0..7
    const int t    = lane & 3;      // 0..3
    const int wrow = (wid & 3) * 32;    // 0,32,64,96
    const int wcol = (wid >> 2) * 32;   // 0,32

    // staging indices
    const int srow = tid >> 3;          // 0..31
    const int sc4  = (tid & 7) * 4;     // 0..28 step 4

    const int K2 = K - K1;
    const int NP = K / GBK;

    float acc[2][4][4];
#pragma unroll
    for (int mt = 0; mt < 2; mt++)
#pragma unroll
        for (int nt = 0; nt < 4; nt++)
#pragma unroll
            for (int i = 0; i < 4; i++) acc[mt][nt][i] = 0.f;

    float4 ra[4], rb[2];

    // --- load panel 0 into regs, store to buf 0 (K1 >= GBK always) ---
    {
#pragma unroll
        for (int i = 0; i < 4; i++)
            ra[i] = *reinterpret_cast<const float4*>(
                A + (size_t)(row0 + srow + 32 * i) * K1 + sc4);
#pragma unroll
        for (int i = 0; i < 2; i++)
            rb[i] = *reinterpret_cast<const float4*>(
                Bm + (size_t)(col0 + srow + 32 * i) * K + sc4);
#pragma unroll
        for (int i = 0; i < 4; i++)
            store_tf32_4(&sm->As[0][srow + 32 * i][sc4], ra[i]);
#pragma unroll
        for (int i = 0; i < 2; i++)
            store_tf32_4(&sm->Bs[0][srow + 32 * i][sc4], rb[i]);
    }
    __syncthreads();

    for (int p = 0; p < NP; p++) {
        // prefetch next panel into regs
        if (p + 1 < NP) {
            const int k0 = (p + 1) * GBK;
            const float* srcA = A; int pitchA = K1; int kcolA = k0;
            if (A2 != nullptr && k0 >= K1) { srcA = A2; pitchA = K2; kcolA = k0 - K1; }
#pragma unroll
            for (int i = 0; i < 4; i++)
                ra[i] = *reinterpret_cast<const float4*>(
                    srcA + (size_t)(row0 + srow + 32 * i) * pitchA + kcolA + sc4);
#pragma unroll
            for (int i = 0; i < 2; i++)
                rb[i] = *reinterpret_cast<const float4*>(
                    Bm + (size_t)(col0 + srow + 32 * i) * K + k0 + sc4);
        }

        // compute on buffer p&1
        const float* ab = &sm->As[p & 1][0][0];
        const float* bb = &sm->Bs[p & 1][0][0];
#pragma unroll
        for (int kk = 0; kk < GBK; kk += 8) {
            uint32_t af[2][4], bf[4][2];
#pragma unroll
            for (int mt = 0; mt < 2; mt++) {
                const int r = wrow + 16 * mt + g;
                af[mt][0] = __float_as_uint(ab[(r)     * SPITCH + kk + t]);
                af[mt][1] = __float_as_uint(ab[(r + 8) * SPITCH + kk + t]);
                af[mt][2] = __float_as_uint(ab[(r)     * SPITCH + kk + t + 4]);
                af[mt][3] = __float_as_uint(ab[(r + 8) * SPITCH + kk + t + 4]);
            }
#pragma unroll
            for (int nt = 0; nt < 4; nt++) {
                const int n = wcol + 8 * nt + g;
                bf[nt][0] = __float_as_uint(bb[n * SPITCH + kk + t]);
                bf[nt][1] = __float_as_uint(bb[n * SPITCH + kk + t + 4]);
            }
#pragma unroll
            for (int mt = 0; mt < 2; mt++)
#pragma unroll
                for (int nt = 0; nt < 4; nt++)
                    mma_tf32(acc[mt][nt][0], acc[mt][nt][1],
                             acc[mt][nt][2], acc[mt][nt][3],
                             af[mt][0], af[mt][1], af[mt][2], af[mt][3],
                             bf[nt][0], bf[nt][1]);
        }

        // store prefetched panel to the other buffer
        if (p + 1 < NP) {
            const int nb = (p + 1) & 1;
#pragma unroll
            for (int i = 0; i < 4; i++)
                store_tf32_4(&sm->As[nb][srow + 32 * i][sc4], ra[i]);
#pragma unroll
            for (int i = 0; i < 2; i++)
                store_tf32_4(&sm->Bs[nb][srow + 32 * i][sc4], rb[i]);
        }
        __syncthreads();
    }

    // epilogue
#pragma unroll
    for (int mt = 0; mt < 2; mt++) {
        const int row = row0 + wrow + 16 * mt + g;
#pragma unroll
        for (int nt = 0; nt < 4; nt++) {
            const int col = col0 + wcol + 8 * nt + 2 * t;
            float b0v = 0.f, b1v = 0.f;
            if (bias != nullptr) { b0v = bias[col]; b1v = bias[col + 1]; }
            C[(size_t)row * N + col]           = acc[mt][nt][0] + b0v;
            C[(size_t)row * N + col + 1]       = acc[mt][nt][1] + b1v;
            C[(size_t)(row + 8) * N + col]     = acc[mt][nt][2] + b0v;
            C[(size_t)(row + 8) * N + col + 1] = acc[mt][nt][3] + b1v;
        }
    }
}

// merged k1+k2: grid (4, 32). by<16 -> wq GEMM, else uh GEMM.
__global__ __launch_bounds__(256) void gemm_k1k2_kernel(
    const float* __restrict__ inputs, const float* __restrict__ Wq,
    const float* __restrict__ mems,   const float* __restrict__ Wc,
    const float* __restrict__ bc,
    float* __restrict__ owq, float* __restrict__ ouh)
{
    extern __shared__ GemmSmem sm_dyn[];
    GemmSmem* sm = sm_dyn;
    const int bx = blockIdx.x, by = blockIdx.y;
    if (by < 16) {
        gemm_body(sm, inputs, nullptr, IN_DIM, Wq, nullptr, owq,
                  MEM_DIM, IN_DIM, by * GBM, bx * GBN);
    } else {
        gemm_body(sm, mems, nullptr, MEM_DIM, Wc, bc, ouh,
                  MEM_DIM, MEM_DIM, (by - 16) * GBM, bx * GBN);
    }
}

// k4: dual-A output projection. grid (8, 16)
__global__ __launch_bounds__(256) void gemm_out_kernel(
    const float* __restrict__ Cmat, const float* __restrict__ inputs,
    const float* __restrict__ Wout, const float* __restrict__ bout,
    float* __restrict__ attn_h)
{
    extern __shared__ GemmSmem sm_dyn[];
    GemmSmem* sm = sm_dyn;
    gemm_body(sm, Cmat, inputs, MEM_DIM, Wout, bout, attn_h,
              IN_DIM, MEM_DIM + IN_DIM, blockIdx.y * GBM, blockIdx.x * GBN);
}

// ---------------------------------------------------------------------------
// Fused attention core: scores -> tanh -> dot(v) -> masked softmax -> context
// Grid: (37, B) = 148 CTAs (one per SM), 512 threads. Thread owns one s.
// TTILE=14 rows per CTA; last tile of each batch has 8 valid rows.
// cp.async double-buffered uh tiles, s-major pitch-20 layout.
// ---------------------------------------------------------------------------
#define TTILE 14
#define NTILES_T 37           // ceil(512/14) = 37; 36*14=504, last tile 8 rows
#define DTILE 16
#define UPITCH 20
#define UBUF_ELEMS (SS * UPITCH)          // 10240 floats per buffer
#define ATTN_SMEM_FLOATS (2 * UBUF_ELEMS + TTILE * MEM_DIM + MEM_DIM + TTILE * 16)
#define ATTN_SMEM_BYTES  (ATTN_SMEM_FLOATS * 4)

__device__ __forceinline__ float tanh_fast(float x) {
    float y;
    asm("tanh.approx.f32 %0, %1;" : "=f"(y) : "f"(x));
    return y;
}

__device__ __forceinline__ void cp_async16(void* sdst, const void* gsrc) {
    uint32_t sa = (uint32_t)__cvta_generic_to_shared(sdst);
    asm volatile("cp.async.ca.shared.global [%0], [%1], 16;\n" :: "r"(sa), "l"(gsrc));
}
#define CP_COMMIT()  asm volatile("cp.async.commit_group;\n")
#define CP_WAIT(N)   asm volatile("cp.async.wait_group %0;\n" :: "n"(N))

__device__ __forceinline__ void prefetch_uh(
    const float* __restrict__ uh_b, float* ubuf, int d0, int tid)
{
    const int c  = tid & 3;
    const int s0 = tid >> 2;
#pragma unroll
    for (int it = 0; it < 4; it++) {
        const int s = s0 + it * 128;
        cp_async16(ubuf + s * UPITCH + c * 4,
                   uh_b + ((size_t)s << 8) + d0 + c * 4);
    }
}

__global__ __launch_bounds__(512) void attn_core_kernel(
    const float* __restrict__ wq,        // [B,T,256]
    const float* __restrict__ uh,        // [B,S,256]
    const float* __restrict__ mems,      // [B,S,256]
    const int*   __restrict__ mem_masks, // [B]
    const float* __restrict__ v,         // [256]
    float* __restrict__ align_out,       // [B,T,S]
    float* __restrict__ c_out)           // [B,T,256]
{
    extern __shared__ float sdyn[];
    float* ubuf0 = sdyn;                          // [512][20]
    float* ubuf1 = sdyn + UBUF_ELEMS;             // [512][20]
    float* wq_s  = sdyn + 2 * UBUF_ELEMS;         // [14][256]
    float* v_s   = wq_s + TTILE * MEM_DIM;        // [256]
    float* red_s = v_s + MEM_DIM;                 // [14][16]
    float* pbuf  = ubuf0;                         // reused for p: [14][512]

    const int tid  = threadIdx.x;
    const int b    = blockIdx.y;
    const int t0   = blockIdx.x * TTILE;
    const int my_s = tid;
    const int lane = tid & 31;
    const int wid  = tid >> 5;

    const float* uh_b = uh + ((size_t)b * SS << 8);

    // kick off first uh tile ASAP
    prefetch_uh(uh_b, ubuf0, 0, tid);
    CP_COMMIT();

    // stage wq rows (14*64 = 896 float4 over 512 threads) + v
    for (int i = tid; i < TTILE * 64; i += 512) {
        const int t  = i >> 6;
        const int c4 = (i & 63) * 4;
        float4 val = make_float4(0.f, 0.f, 0.f, 0.f);
        if (t0 + t < TT_ALL)
            val = *reinterpret_cast<const float4*>(
                wq + ((size_t)(b * TT_ALL + t0 + t) << 8) + c4);
        *reinterpret_cast<float4*>(wq_s + t * MEM_DIM + c4) = val;
    }
    if (tid < 64)
        *reinterpret_cast<float4*>(v_s + tid * 4) =
            *reinterpret_cast<const float4*>(v + tid * 4);

    const int mlen = mem_masks[b];

    float acc[TTILE];
#pragma unroll
    for (int t = 0; t < TTILE; t++) acc[t] = 0.f;

    // ---- score phase with cp.async double buffering ----
#pragma unroll 1
    for (int tile = 0; tile < MEM_DIM / DTILE; tile++) {
        const int d0 = tile * DTILE;
        if (tile + 1 < MEM_DIM / DTILE) {
            prefetch_uh(uh_b, (tile & 1) ? ubuf0 : ubuf1, d0 + DTILE, tid);
            CP_COMMIT();
            CP_WAIT(1);
        } else {
            CP_WAIT(0);
        }
        __syncthreads();

        const float* ub = ((tile & 1) ? ubuf1 : ubuf0) + my_s * UPITCH;
#pragma unroll
        for (int q = 0; q < 4; q++) {
            const float4 u4 = *reinterpret_cast<const float4*>(ub + q * 4);
            const float4 v4 = *reinterpret_cast<const float4*>(v_s + d0 + q * 4);
#pragma unroll
            for (int t = 0; t < TTILE; t++) {
                const float4 w4 = *reinterpret_cast<const float4*>(
                    wq_s + t * MEM_DIM + d0 + q * 4);
                float a = acc[t];
                a = fmaf(tanh_fast(w4.x + u4.x), v4.x, a);
                a = fmaf(tanh_fast(w4.y + u4.y), v4.y, a);
                a = fmaf(tanh_fast(w4.z + u4.z), v4.z, a);
                a = fmaf(tanh_fast(w4.w + u4.w), v4.w, a);
                acc[t] = a;
            }
        }
        __syncthreads();
    }

    // ---- masked softmax over s (512 threads) ----
    const bool valid = (my_s < mlen);
    float sc[TTILE];
#pragma unroll
    for (int t = 0; t < TTILE; t++) sc[t] = valid ? acc[t] : -1e30f;

    float mx[TTILE];
#pragma unroll
    for (int t = 0; t < TTILE; t++) {
        float m = sc[t];
#pragma unroll
        for (int o = 16; o > 0; o >>= 1) m = fmaxf(m, __shfl_xor_sync(0xffffffffu, m, o));
        if (lane == 0) red_s[t * 16 + wid] = m;
    }
    __syncthreads();
#pragma unroll
    for (int t = 0; t < TTILE; t++) {
        float m = red_s[t * 16];
#pragma unroll
        for (int i = 1; i < 16; i++) m = fmaxf(m, red_s[t * 16 + i]);
        mx[t] = m;
    }
    __syncthreads();   // before reusing red_s

    float e[TTILE];
#pragma unroll
    for (int t = 0; t < TTILE; t++)
        e[t] = valid ? __expf(sc[t] - mx[t]) : 0.f;

#pragma unroll
    for (int t = 0; t < TTILE; t++) {
        float s = e[t];
#pragma unroll
        for (int o = 16; o > 0; o >>= 1) s += __shfl_xor_sync(0xffffffffu, s, o);
        if (lane == 0) red_s[t * 16 + wid] = s;
    }
    __syncthreads();

    float p[TTILE];
#pragma unroll
    for (int t = 0; t < TTILE; t++) {
        float s = 0.f;
#pragma unroll
        for (int i = 0; i < 16; i++) s += red_s[t * 16 + i];
        p[t] = e[t] * (1.0f / s);
    }

    // write align_vectors + stage p into smem (pbuf reuses ubuf0)
#pragma unroll
    for (int t = 0; t < TTILE; t++) {
        if (t0 + t < TT_ALL)
            align_out[((size_t)(b * TT_ALL + t0 + t) << 9) + my_s] = p[t];
        pbuf[t * SS + my_s] = p[t];
    }
    __syncthreads();

    // ---- context: c[t,m] = sum_s p[t,s] * mems[b,s,m] ----
    const int m    = tid & 255;
    const int half = tid >> 8;
    float cacc[TTILE];
#pragma unroll
    for (int t = 0; t < TTILE; t++) cacc[t] = 0.f;

    const float* mb = mems + ((size_t)(b * SS + half * 256) << 8) + m;
    const float* pb = pbuf + half * 256;
#pragma unroll 2
    for (int s4 = 0; s4 < 64; s4++) {
        const float mv0 = mb[(size_t)(s4 * 4 + 0) << 8];
        const float mv1 = mb[(size_t)(s4 * 4 + 1) << 8];
        const float mv2 = mb[(size_t)(s4 * 4 + 2) << 8];
        const float mv3 = mb[(size_t)(s4 * 4 + 3) << 8];
#pragma unroll
        for (int t = 0; t < TTILE; t++) {
            const float4 pv = *reinterpret_cast<const float4*>(pb + t * SS + s4 * 4);
            cacc[t] = fmaf(pv.x, mv0,
                      fmaf(pv.y, mv1,
                      fmaf(pv.z, mv2,
                      fmaf(pv.w, mv3, cacc[t]))));
        }
    }

    if (half == 1) {
#pragma unroll
        for (int t = 0; t < TTILE; t++) wq_s[t * MEM_DIM + m] = cacc[t];
    }
    __syncthreads();
    if (half == 0) {
#pragma unroll
        for (int t = 0; t < TTILE; t++)
            if (t0 + t < TT_ALL)
                c_out[((size_t)(b * TT_ALL + t0 + t) << 8) + m] =
                    cacc[t] + wq_s[t * MEM_DIM + m];
    }
}

// ---------------------------------------------------------------------------
// Launch
// ---------------------------------------------------------------------------
extern "C" void kernel_launch(void* const* d_in, const int* in_sizes, int n_in,
                              void* d_out, int out_size)
{
    const float* inputs    = (const float*)d_in[0];   // [B,T,512]
    const float* mems      = (const float*)d_in[1];   // [B,S,256]
    const int*   mem_masks = (const int*)  d_in[2];   // [B]
    const float* Wq        = (const float*)d_in[3];   // [256,512]
    const float* Wc        = (const float*)d_in[4];   // [256,256]
    const float* bc        = (const float*)d_in[5];   // [256]
    const float* v         = (const float*)d_in[6];   // [256]
    const float* Wout      = (const float*)d_in[7];   // [512,768]
    const float* bout      = (const float*)d_in[8];   // [512]

    float* out = (float*)d_out;
    float* attn_h    = out;                                   // [B,T,512]
    float* align_vec = out + (size_t)BB * TT_ALL * IN_DIM;    // [B,T,S]

    float *p_wq = nullptr, *p_uh = nullptr, *p_c = nullptr;
    cudaGetSymbolAddress((void**)&p_wq, g_wq);
    cudaGetSymbolAddress((void**)&p_uh, g_uh);
    cudaGetSymbolAddress((void**)&p_c,  g_c);

    cudaFuncSetAttribute(attn_core_kernel,
                         cudaFuncAttributeMaxDynamicSharedMemorySize,
                         ATTN_SMEM_BYTES);
    cudaFuncSetAttribute(gemm_k1k2_kernel,
                         cudaFuncAttributeMaxDynamicSharedMemorySize,
                         GEMM_SMEM_BYTES);
    cudaFuncSetAttribute(gemm_out_kernel,
                         cudaFuncAttributeMaxDynamicSharedMemorySize,
                         GEMM_SMEM_BYTES);

    // 1+2) merged wq / uh GEMMs  (grid 4 x 32 = 128 CTAs)
    gemm_k1k2_kernel<<<dim3(MEM_DIM / GBN, 32), 256, GEMM_SMEM_BYTES>>>(
        inputs, Wq, mems, Wc, bc, p_wq, p_uh);

    // 3) fused tanh-score / softmax / context (grid 37 x 4 = 148 CTAs)
    attn_core_kernel<<<dim3(NTILES_T, BB), 512, ATTN_SMEM_BYTES>>>(
        p_wq, p_uh, mems, mem_masks, v, align_vec, p_c);

    // 4) attn_h = [c, inputs] @ Wout^T + bout  (grid 8 x 16 = 128 CTAs)
    gemm_out_kernel<<<dim3(IN_DIM / GBN, (BB * TT_ALL) / GBM), 256, GEMM_SMEM_BYTES>>>(
        p_c, inputs, Wout, bout, attn_h);
}

// round 7
// speedup vs baseline: 1.7942x; 1.0740x over previous
#include <cuda_runtime.h>
#include <cuda_bf16.h>
#include <cstdint>

// Problem constants
#define BB      4
#define TT_ALL  512
#define SS      512
#define IN_DIM  512
#define MEM_DIM 256

// Scratch (device globals; no allocations allowed)
__device__ __align__(16) float g_wq[BB * TT_ALL * MEM_DIM];   // [B,T,256]
__device__ __align__(16) float g_uh[BB * SS * MEM_DIM];       // [B,S,256]
__device__ __align__(16) float g_c [BB * TT_ALL * MEM_DIM];   // [B,T,256]

// ---------------------------------------------------------------------------
// TF32 tensor-core NT GEMM (R4 measured-best config):
// C[M,N] = Acat[M,K] * B[N,K]^T (+bias). CTA tile 64x64, BK=32,
// 128 threads = 4 warps, warp tile 32x32. Static smem 36 KB.
// ---------------------------------------------------------------------------
#define GBM 64
#define GBN 64
#define GBK 32
#define SPITCH 36

__device__ __forceinline__ uint32_t f2tf32(float f) {
    uint32_t o;
    asm("cvt.rna.tf32.f32 %0, %1;" : "=r"(o) : "f"(f));
    return o;
}

__device__ __forceinline__ void mma_tf32(
    float& c0, float& c1, float& c2, float& c3,
    uint32_t a0, uint32_t a1, uint32_t a2, uint32_t a3,
    uint32_t b0, uint32_t b1)
{
    asm volatile(
        "mma.sync.aligned.m16n8k8.row.col.f32.tf32.tf32.f32 "
        "{%0,%1,%2,%3}, {%4,%5,%6,%7}, {%8,%9}, {%0,%1,%2,%3};\n"
        : "+f"(c0), "+f"(c1), "+f"(c2), "+f"(c3)
        : "r"(a0), "r"(a1), "r"(a2), "r"(a3), "r"(b0), "r"(b1));
}

struct GemmSmem {
    float As[2][GBM][SPITCH];
    float Bs[2][GBN][SPITCH];
};

__device__ __forceinline__ void gemm_body(
    GemmSmem* sm,
    const float* __restrict__ A, const float* __restrict__ A2, int K1,
    const float* __restrict__ Bm, const float* __restrict__ bias,
    float* __restrict__ C, int N, int K, int row0, int col0)
{
    const int tid  = threadIdx.x;
    const int wid  = tid >> 5;
    const int lane = tid & 31;
    const int g    = lane >> 2;
    const int t    = lane & 3;
    const int wrow = (wid & 1) * 32;
    const int wcol = (wid >> 1) * 32;

    const int srow = tid >> 3;          // 0..15
    const int sc4  = (tid & 7) * 4;     // 0..28 step 4

    const int K2 = K - K1;
    const int NP = K / GBK;

    float acc[2][4][4];
#pragma unroll
    for (int mt = 0; mt < 2; mt++)
#pragma unroll
        for (int nt = 0; nt < 4; nt++)
#pragma unroll
            for (int i = 0; i < 4; i++) acc[mt][nt][i] = 0.f;

    float4 ra[4], rb[4];

    {
#pragma unroll
        for (int i = 0; i < 4; i++) {
            ra[i] = *reinterpret_cast<const float4*>(
                A + (size_t)(row0 + srow + 16 * i) * K1 + sc4);
            rb[i] = *reinterpret_cast<const float4*>(
                Bm + (size_t)(col0 + srow + 16 * i) * K + sc4);
        }
#pragma unroll
        for (int i = 0; i < 4; i++) {
            float* pa = &sm->As[0][srow + 16 * i][sc4];
            pa[0] = __uint_as_float(f2tf32(ra[i].x));
            pa[1] = __uint_as_float(f2tf32(ra[i].y));
            pa[2] = __uint_as_float(f2tf32(ra[i].z));
            pa[3] = __uint_as_float(f2tf32(ra[i].w));
            float* pb = &sm->Bs[0][srow + 16 * i][sc4];
            pb[0] = __uint_as_float(f2tf32(rb[i].x));
            pb[1] = __uint_as_float(f2tf32(rb[i].y));
            pb[2] = __uint_as_float(f2tf32(rb[i].z));
            pb[3] = __uint_as_float(f2tf32(rb[i].w));
        }
    }
    __syncthreads();

    for (int p = 0; p < NP; p++) {
        if (p + 1 < NP) {
            const int k0 = (p + 1) * GBK;
            const float* srcA = A; int pitchA = K1; int kcolA = k0;
            if (A2 != nullptr && k0 >= K1) { srcA = A2; pitchA = K2; kcolA = k0 - K1; }
#pragma unroll
            for (int i = 0; i < 4; i++) {
                ra[i] = *reinterpret_cast<const float4*>(
                    srcA + (size_t)(row0 + srow + 16 * i) * pitchA + kcolA + sc4);
                rb[i] = *reinterpret_cast<const float4*>(
                    Bm + (size_t)(col0 + srow + 16 * i) * K + k0 + sc4);
            }
        }

        const float* ab = &sm->As[p & 1][0][0];
        const float* bb = &sm->Bs[p & 1][0][0];
#pragma unroll
        for (int kk = 0; kk < GBK; kk += 8) {
            uint32_t af[2][4], bf[4][2];
#pragma unroll
            for (int mt = 0; mt < 2; mt++) {
                const int r = wrow + 16 * mt + g;
                af[mt][0] = __float_as_uint(ab[(r)     * SPITCH + kk + t]);
                af[mt][1] = __float_as_uint(ab[(r + 8) * SPITCH + kk + t]);
                af[mt][2] = __float_as_uint(ab[(r)     * SPITCH + kk + t + 4]);
                af[mt][3] = __float_as_uint(ab[(r + 8) * SPITCH + kk + t + 4]);
            }
#pragma unroll
            for (int nt = 0; nt < 4; nt++) {
                const int n = wcol + 8 * nt + g;
                bf[nt][0] = __float_as_uint(bb[n * SPITCH + kk + t]);
                bf[nt][1] = __float_as_uint(bb[n * SPITCH + kk + t + 4]);
            }
#pragma unroll
            for (int mt = 0; mt < 2; mt++)
#pragma unroll
                for (int nt = 0; nt < 4; nt++)
                    mma_tf32(acc[mt][nt][0], acc[mt][nt][1],
                             acc[mt][nt][2], acc[mt][nt][3],
                             af[mt][0], af[mt][1], af[mt][2], af[mt][3],
                             bf[nt][0], bf[nt][1]);
        }

        if (p + 1 < NP) {
            const int nb = (p + 1) & 1;
#pragma unroll
            for (int i = 0; i < 4; i++) {
                float* pa = &sm->As[nb][srow + 16 * i][sc4];
                pa[0] = __uint_as_float(f2tf32(ra[i].x));
                pa[1] = __uint_as_float(f2tf32(ra[i].y));
                pa[2] = __uint_as_float(f2tf32(ra[i].z));
                pa[3] = __uint_as_float(f2tf32(ra[i].w));
                float* pb = &sm->Bs[nb][srow + 16 * i][sc4];
                pb[0] = __uint_as_float(f2tf32(rb[i].x));
                pb[1] = __uint_as_float(f2tf32(rb[i].y));
                pb[2] = __uint_as_float(f2tf32(rb[i].z));
                pb[3] = __uint_as_float(f2tf32(rb[i].w));
            }
        }
        __syncthreads();
    }

#pragma unroll
    for (int mt = 0; mt < 2; mt++) {
        const int row = row0 + wrow + 16 * mt + g;
#pragma unroll
        for (int nt = 0; nt < 4; nt++) {
            const int col = col0 + wcol + 8 * nt + 2 * t;
            float b0v = 0.f, b1v = 0.f;
            if (bias != nullptr) { b0v = bias[col]; b1v = bias[col + 1]; }
            C[(size_t)row * N + col]           = acc[mt][nt][0] + b0v;
            C[(size_t)row * N + col + 1]       = acc[mt][nt][1] + b1v;
            C[(size_t)(row + 8) * N + col]     = acc[mt][nt][2] + b0v;
            C[(size_t)(row + 8) * N + col + 1] = acc[mt][nt][3] + b1v;
        }
    }
}

// merged k1+k2: grid (4, 64). by<32 -> wq GEMM, else uh GEMM.
__global__ __launch_bounds__(128) void gemm_k1k2_kernel(
    const float* __restrict__ inputs, const float* __restrict__ Wq,
    const float* __restrict__ mems,   const float* __restrict__ Wc,
    const float* __restrict__ bc,
    float* __restrict__ owq, float* __restrict__ ouh)
{
    __shared__ GemmSmem sm;
    const int bx = blockIdx.x, by = blockIdx.y;
    if (by < 32) {
        gemm_body(&sm, inputs, nullptr, IN_DIM, Wq, nullptr, owq,
                  MEM_DIM, IN_DIM, by * GBM, bx * GBN);
    } else {
        gemm_body(&sm, mems, nullptr, MEM_DIM, Wc, bc, ouh,
                  MEM_DIM, MEM_DIM, (by - 32) * GBM, bx * GBN);
    }
}

// k4: dual-A output projection. grid (8, 32)
__global__ __launch_bounds__(128) void gemm_out_kernel(
    const float* __restrict__ Cmat, const float* __restrict__ inputs,
    const float* __restrict__ Wout, const float* __restrict__ bout,
    float* __restrict__ attn_h)
{
    __shared__ GemmSmem sm;
    gemm_body(&sm, Cmat, inputs, MEM_DIM, Wout, bout, attn_h,
              IN_DIM, MEM_DIM + IN_DIM, blockIdx.y * GBM, blockIdx.x * GBN);
}

// ---------------------------------------------------------------------------
// Fused attention core: scores -> tanh -> dot(v) -> masked softmax -> context
// Grid: (37, B) = 148 CTAs (one per SM), 512 threads.
// Score: thread owns one s, cp.async double-buffered uh tiles.
// Context: tensor-core [16 x 512] x [512 x 256] per CTA, mems streamed
// through smem in 32-row chunks (cp.async double-buffered).
// ---------------------------------------------------------------------------
#define TTILE 14
#define NTILES_T 37
#define DTILE 16
#define UPITCH 20
#define UBUF_ELEMS (SS * UPITCH)          // 10240 floats
#define PBP   520                          // pbuf pitch (conflict-free A frags)
#define MROWS 32                           // mems chunk rows
#define MPITCH 264                         // mems tile pitch (conflict-free B frags)
#define MBUF_ELEMS (MROWS * MPITCH)        // 8448 floats
#define ATTN_SMEM_FLOATS (2 * UBUF_ELEMS + TTILE * MEM_DIM + MEM_DIM + TTILE * 16 \
                          + 2 * MBUF_ELEMS)
#define ATTN_SMEM_BYTES  (ATTN_SMEM_FLOATS * 4)

__device__ __forceinline__ float tanh_fast(float x) {
    float y;
    asm("tanh.approx.f32 %0, %1;" : "=f"(y) : "f"(x));
    return y;
}

__device__ __forceinline__ void cp_async16(void* sdst, const void* gsrc) {
    uint32_t sa = (uint32_t)__cvta_generic_to_shared(sdst);
    asm volatile("cp.async.ca.shared.global [%0], [%1], 16;\n" :: "r"(sa), "l"(gsrc));
}
#define CP_COMMIT()  asm volatile("cp.async.commit_group;\n")
#define CP_WAIT(N)   asm volatile("cp.async.wait_group %0;\n" :: "n"(N))

__device__ __forceinline__ void prefetch_uh(
    const float* __restrict__ uh_b, float* ubuf, int d0, int tid)
{
    const int c  = tid & 3;
    const int s0 = tid >> 2;
#pragma unroll
    for (int it = 0; it < 4; it++) {
        const int s = s0 + it * 128;
        cp_async16(ubuf + s * UPITCH + c * 4,
                   uh_b + ((size_t)s << 8) + d0 + c * 4);
    }
}

// stage one 32-row mems chunk into smem tile (pitch MPITCH)
__device__ __forceinline__ void stage_mems(
    const float* __restrict__ memb, float* mbuf, int chunk, int tid)
{
#pragma unroll
    for (int j = 0; j < 4; j++) {
        const int i  = tid + j * 512;        // 0..2047 float4 index
        const int r  = i >> 6;               // 0..31
        const int c4 = (i & 63) * 4;         // 0..252
        cp_async16(mbuf + r * MPITCH + c4,
                   memb + ((size_t)(chunk * MROWS + r) << 8) + c4);
    }
}

__global__ __launch_bounds__(512) void attn_core_kernel(
    const float* __restrict__ wq,        // [B,T,256]
    const float* __restrict__ uh,        // [B,S,256]
    const float* __restrict__ mems,      // [B,S,256]
    const int*   __restrict__ mem_masks, // [B]
    const float* __restrict__ v,         // [256]
    float* __restrict__ align_out,       // [B,T,S]
    float* __restrict__ c_out)           // [B,T,256]
{
    extern __shared__ float sdyn[];
    float* ubuf0 = sdyn;                          // [512][20]
    float* ubuf1 = sdyn + UBUF_ELEMS;             // [512][20]
    float* wq_s  = sdyn + 2 * UBUF_ELEMS;         // [14][256]
    float* v_s   = wq_s + TTILE * MEM_DIM;        // [256]
    float* red_s = v_s + MEM_DIM;                 // [14][16]
    float* mbuf0 = red_s + TTILE * 16;            // [32][264]
    float* mbuf1 = mbuf0 + MBUF_ELEMS;            // [32][264]
    float* pbuf  = ubuf0;                         // reused for p: [16][PBP]

    const int tid  = threadIdx.x;
    const int b    = blockIdx.y;
    const int t0   = blockIdx.x * TTILE;
    const int my_s = tid;
    const int lane = tid & 31;
    const int wid  = tid >> 5;

    const float* uh_b = uh + ((size_t)b * SS << 8);

    // kick off first uh tile ASAP
    prefetch_uh(uh_b, ubuf0, 0, tid);
    CP_COMMIT();

    // stage wq rows + v
    for (int i = tid; i < TTILE * 64; i += 512) {
        const int t  = i >> 6;
        const int c4 = (i & 63) * 4;
        float4 val = make_float4(0.f, 0.f, 0.f, 0.f);
        if (t0 + t < TT_ALL)
            val = *reinterpret_cast<const float4*>(
                wq + ((size_t)(b * TT_ALL + t0 + t) << 8) + c4);
        *reinterpret_cast<float4*>(wq_s + t * MEM_DIM + c4) = val;
    }
    if (tid < 64)
        *reinterpret_cast<float4*>(v_s + tid * 4) =
            *reinterpret_cast<const float4*>(v + tid * 4);

    const int mlen = mem_masks[b];

    float acc[TTILE];
#pragma unroll
    for (int t = 0; t < TTILE; t++) acc[t] = 0.f;

    // ---- score phase with cp.async double buffering ----
#pragma unroll 1
    for (int tile = 0; tile < MEM_DIM / DTILE; tile++) {
        const int d0 = tile * DTILE;
        if (tile + 1 < MEM_DIM / DTILE) {
            prefetch_uh(uh_b, (tile & 1) ? ubuf0 : ubuf1, d0 + DTILE, tid);
            CP_COMMIT();
            CP_WAIT(1);
        } else {
            CP_WAIT(0);
        }
        __syncthreads();

        const float* ub = ((tile & 1) ? ubuf1 : ubuf0) + my_s * UPITCH;
#pragma unroll
        for (int q = 0; q < 4; q++) {
            const float4 u4 = *reinterpret_cast<const float4*>(ub + q * 4);
            const float4 v4 = *reinterpret_cast<const float4*>(v_s + d0 + q * 4);
#pragma unroll
            for (int t = 0; t < TTILE; t++) {
                const float4 w4 = *reinterpret_cast<const float4*>(
                    wq_s + t * MEM_DIM + d0 + q * 4);
                float a = acc[t];
                a = fmaf(tanh_fast(w4.x + u4.x), v4.x, a);
                a = fmaf(tanh_fast(w4.y + u4.y), v4.y, a);
                a = fmaf(tanh_fast(w4.z + u4.z), v4.z, a);
                a = fmaf(tanh_fast(w4.w + u4.w), v4.w, a);
                acc[t] = a;
            }
        }
        __syncthreads();
    }

    // ---- masked softmax over s (512 threads) ----
    const bool valid = (my_s < mlen);
    float sc[TTILE];
#pragma unroll
    for (int t = 0; t < TTILE; t++) sc[t] = valid ? acc[t] : -1e30f;

    float mx[TTILE];
#pragma unroll
    for (int t = 0; t < TTILE; t++) {
        float m = sc[t];
#pragma unroll
        for (int o = 16; o > 0; o >>= 1) m = fmaxf(m, __shfl_xor_sync(0xffffffffu, m, o));
        if (lane == 0) red_s[t * 16 + wid] = m;
    }
    __syncthreads();
#pragma unroll
    for (int t = 0; t < TTILE; t++) {
        float m = red_s[t * 16];
#pragma unroll
        for (int i = 1; i < 16; i++) m = fmaxf(m, red_s[t * 16 + i]);
        mx[t] = m;
    }
    __syncthreads();

    float e[TTILE];
#pragma unroll
    for (int t = 0; t < TTILE; t++)
        e[t] = valid ? __expf(sc[t] - mx[t]) : 0.f;

#pragma unroll
    for (int t = 0; t < TTILE; t++) {
        float s = e[t];
#pragma unroll
        for (int o = 16; o > 0; o >>= 1) s += __shfl_xor_sync(0xffffffffu, s, o);
        if (lane == 0) red_s[t * 16 + wid] = s;
    }
    __syncthreads();

    float p[TTILE];
#pragma unroll
    for (int t = 0; t < TTILE; t++) {
        float s = 0.f;
#pragma unroll
        for (int i = 0; i < 16; i++) s += red_s[t * 16 + i];
        p[t] = e[t] * (1.0f / s);
    }

    // write align_vectors + stage p (tf32-rounded) into pbuf [16][PBP]
#pragma unroll
    for (int t = 0; t < TTILE; t++) {
        if (t0 + t < TT_ALL)
            align_out[((size_t)(b * TT_ALL + t0 + t) << 9) + my_s] = p[t];
        pbuf[t * PBP + my_s] = __uint_as_float(f2tf32(p[t]));
    }
    // zero pad rows 14,15 of the A tile
    for (int i = tid; i < 2 * PBP; i += 512)
        pbuf[TTILE * PBP + i] = 0.f;
    __syncthreads();

    // ---- context via tensor cores: c[t,m] = sum_s p[t,s] * mems[b,s,m] ----
    // Each of 16 warps owns 16 m-columns (two n8 tiles).
    const float* memb = mems + ((size_t)b * SS << 8);
    const int g  = lane >> 2;
    const int tq = lane & 3;
    const int wn = wid * 16;

    float ca[4] = {0.f, 0.f, 0.f, 0.f};
    float cb[4] = {0.f, 0.f, 0.f, 0.f};

    stage_mems(memb, mbuf0, 0, tid);
    CP_COMMIT();

#pragma unroll 1
    for (int ch = 0; ch < SS / MROWS; ch++) {
        if (ch + 1 < SS / MROWS) {
            stage_mems(memb, (ch & 1) ? mbuf0 : mbuf1, ch + 1, tid);
            CP_COMMIT();
            CP_WAIT(1);
        } else {
            CP_WAIT(0);
        }
        __syncthreads();

        const float* mb = (ch & 1) ? mbuf1 : mbuf0;
        const int sbase = ch * MROWS;
#pragma unroll
        for (int kk = 0; kk < MROWS; kk += 8) {
            const int sg = sbase + kk;
            uint32_t a0 = __float_as_uint(pbuf[(g)     * PBP + sg + tq]);
            uint32_t a1 = __float_as_uint(pbuf[(g + 8) * PBP + sg + tq]);
            uint32_t a2 = __float_as_uint(pbuf[(g)     * PBP + sg + tq + 4]);
            uint32_t a3 = __float_as_uint(pbuf[(g + 8) * PBP + sg + tq + 4]);

            uint32_t b0 = __float_as_uint(mb[(kk + tq)     * MPITCH + wn + g]);
            uint32_t b1 = __float_as_uint(mb[(kk + tq + 4) * MPITCH + wn + g]);
            mma_tf32(ca[0], ca[1], ca[2], ca[3], a0, a1, a2, a3, b0, b1);

            b0 = __float_as_uint(mb[(kk + tq)     * MPITCH + wn + 8 + g]);
            b1 = __float_as_uint(mb[(kk + tq + 4) * MPITCH + wn + 8 + g]);
            mma_tf32(cb[0], cb[1], cb[2], cb[3], a0, a1, a2, a3, b0, b1);
        }
        __syncthreads();
    }

    // epilogue: write c rows (row g and row g+8 of the 16-row tile)
    {
        const int row0g = t0 + g;
        if (row0g < TT_ALL) {   // g in 0..7 < TTILE always
            float* dst = c_out + ((size_t)(b * TT_ALL + row0g) << 8);
            *reinterpret_cast<float2*>(dst + wn + 2 * tq)     = make_float2(ca[0], ca[1]);
            *reinterpret_cast<float2*>(dst + wn + 8 + 2 * tq) = make_float2(cb[0], cb[1]);
        }
        const int row1g = t0 + g + 8;
        if (g + 8 < TTILE && row1g < TT_ALL) {
            float* dst = c_out + ((size_t)(b * TT_ALL + row1g) << 8);
            *reinterpret_cast<float2*>(dst + wn + 2 * tq)     = make_float2(ca[2], ca[3]);
            *reinterpret_cast<float2*>(dst + wn + 8 + 2 * tq) = make_float2(cb[2], cb[3]);
        }
    }
}

// ---------------------------------------------------------------------------
// Launch
// ---------------------------------------------------------------------------
extern "C" void kernel_launch(void* const* d_in, const int* in_sizes, int n_in,
                              void* d_out, int out_size)
{
    const float* inputs    = (const float*)d_in[0];   // [B,T,512]
    const float* mems      = (const float*)d_in[1];   // [B,S,256]
    const int*   mem_masks = (const int*)  d_in[2];   // [B]
    const float* Wq        = (const float*)d_in[3];   // [256,512]
    const float* Wc        = (const float*)d_in[4];   // [256,256]
    const float* bc        = (const float*)d_in[5];   // [256]
    const float* v         = (const float*)d_in[6];   // [256]
    const float* Wout      = (const float*)d_in[7];   // [512,768]
    const float* bout      = (const float*)d_in[8];   // [512]

    float* out = (float*)d_out;
    float* attn_h    = out;                                   // [B,T,512]
    float* align_vec = out + (size_t)BB * TT_ALL * IN_DIM;    // [B,T,S]

    float *p_wq = nullptr, *p_uh = nullptr, *p_c = nullptr;
    cudaGetSymbolAddress((void**)&p_wq, g_wq);
    cudaGetSymbolAddress((void**)&p_uh, g_uh);
    cudaGetSymbolAddress((void**)&p_c,  g_c);

    cudaFuncSetAttribute(attn_core_kernel,
                         cudaFuncAttributeMaxDynamicSharedMemorySize,
                         ATTN_SMEM_BYTES);

    const int M = BB * TT_ALL;   // 2048

    // 1+2) merged wq / uh GEMMs  (grid 4 x 64 = 256 CTAs, 128 thr)
    gemm_k1k2_kernel<<<dim3(MEM_DIM / GBN, 64), 128>>>(
        inputs, Wq, mems, Wc, bc, p_wq, p_uh);

    // 3) fused tanh-score / softmax / tensor-core context (148 CTAs)
    attn_core_kernel<<<dim3(NTILES_T, BB), 512, ATTN_SMEM_BYTES>>>(
        p_wq, p_uh, mems, mem_masks, v, align_vec, p_c);

    // 4) attn_h = [c, inputs] @ Wout^T + bout  (grid 8 x 32 = 256 CTAs)
    gemm_out_kernel<<<dim3(IN_DIM / GBN, M / GBM), 128>>>(
        p_c, inputs, Wout, bout, attn_h);
}